// round 13
// baseline (speedup 1.0000x reference)
#include <cuda_runtime.h>
#include <math.h>

// ----------------------------------------------------------------------------
// ModulatedDeformableConv2d (DCNv2-style) with residual offset output.
//   B=4, CIN=COUT=128, K=3, S=1, P=1, D=1, H=W=96, MASK_SCALE=2
// d_out: out [4,128,96,96] then offset [4,18,96,96], float32.
// ----------------------------------------------------------------------------

namespace {
constexpr int Bn    = 4;
constexpr int CIN_  = 128;
constexpr int COUT_ = 128;
constexpr int Hd    = 96;
constexpr int Wd    = 96;
constexpr int HW_   = 9216;
constexpr int KKd   = CIN_ * 9;              // 1152
constexpr int OUT_ELEMS = Bn * COUT_ * HW_;  // 4718592
constexpr int KC    = 16;                    // k-chunk (dcn_main)
}

__device__ float g_om[Bn * 27 * HW_];             // offset/mask conv scratch
__device__ __align__(16) float g_wT[KKd * 128];   // weight transposed [kk][oc]

// ---- packed fp32x2 + cp.async helpers --------------------------------------
__device__ __forceinline__ void fma2(unsigned long long& d,
                                     unsigned long long a,
                                     unsigned long long b) {
    asm("fma.rn.f32x2 %0, %1, %2, %0;" : "+l"(d) : "l"(a), "l"(b));
}
__device__ __forceinline__ unsigned long long dup2(float v) {
    unsigned long long r;
    asm("mov.b64 %0, {%1, %1};" : "=l"(r) : "f"(v));
    return r;
}
__device__ __forceinline__ float2 unpk(unsigned long long v) {
    float2 r;
    asm("mov.b64 {%0, %1}, %2;" : "=f"(r.x), "=f"(r.y) : "l"(v));
    return r;
}
__device__ __forceinline__ void cp16(void* dst_smem, const void* src) {
    unsigned d = (unsigned)__cvta_generic_to_shared(dst_smem);
    asm volatile("cp.async.ca.shared.global [%0], [%1], 16;" :: "r"(d), "l"(src));
}
__device__ __forceinline__ void cp_commit() {
    asm volatile("cp.async.commit_group;");
}
__device__ __forceinline__ void cp_wait0() {
    asm volatile("cp.async.wait_group 0;" ::: "memory");
}

// ----------------------------------------------------------------------------
// Kernel 1: blocks 0..767: om = conv3x3(x, w_offmask), 27 ch, pad=1
//           (reads wom directly, transposing on the fly).
//           blocks 768..1055: transpose weight -> g_wT (consumed by kernel 2;
//           no intra-kernel consumer, so no race).
// ----------------------------------------------------------------------------
__global__ __launch_bounds__(128) void offconv_kernel(
    const float* __restrict__ x,
    const float* __restrict__ wom,
    const float* __restrict__ weight,
    float* __restrict__ outp)
{
    const int bx = blockIdx.x;
    const int t  = threadIdx.x;

    if (bx >= 768) {
        // ---- weight transpose tail: 288 blocks x 128 thr x 1 float4
        const int qid  = (bx - 768) * 128 + t;      // 0..36863
        const int idx4 = qid * 4;
        const int kk   = idx4 >> 7;
        const int oc0  = idx4 & 127;
        float4 v;
        v.x = __ldg(weight + (oc0 + 0) * KKd + kk);
        v.y = __ldg(weight + (oc0 + 1) * KKd + kk);
        v.z = __ldg(weight + (oc0 + 2) * KKd + kk);
        v.w = __ldg(weight + (oc0 + 3) * KKd + kk);
        *reinterpret_cast<float4*>(g_wT + idx4) = v;
        return;
    }

    __shared__ __align__(16) float xr[2][4][3][104];  // dup-stored, cols 0..49
    __shared__ __align__(16) float wA[2][4][9][32];   // [c][tap][oc]

    const int wt = bx & 1;
    const int h  = (bx >> 1) % Hd;
    const int b  = bx / (2 * Hd);
    const int w0 = wt * 48;
    const int ty = t >> 4;            // 0..7  -> oc0 = ty*4
    const int tx = t & 15;            // 0..15 -> px0 = tx*3
    const int oc0 = ty * 4;
    const int px0 = tx * 3;

    // zero pad weight columns (oc 27..31) in BOTH buffers once
    for (int e = t; e < 2 * 4 * 9 * 5; e += 128) {
        const int bu = e / 180;
        const int r  = e % 180;
        wA[bu][r / 45][(r % 45) / 5][27 + (r % 45) % 5] = 0.f;
    }

    unsigned long long acc[2][3];
#pragma unroll
    for (int i = 0; i < 2; i++)
#pragma unroll
        for (int j = 0; j < 3; j++) acc[i][j] = 0ull;

    const float* xb = x + b * CIN_ * HW_;
    int buf = 0;

    for (int c0 = 0; c0 < CIN_; c0 += 4, buf ^= 1) {
        // ---- weights: direct transposing loads from wom
#pragma unroll
        for (int i = 0; i < 8; i++) {
            const int e = t + i * 128;
            if (e < 972) {                         // 27 oc x 36 (c,tap)
                const int oc = e / 36;
                const int ck = e % 36;
                wA[buf][ck / 9][ck % 9][oc] =
                    __ldg(wom + oc * KKd + (c0 + ck / 9) * 9 + (ck % 9));
            }
        }
        // ---- row cache (dup-stored): cols w0-1..w0+48 -> idx 0..49
#pragma unroll
        for (int i = 0; i < 5; i++) {
            const int e = t + i * 128;
            if (e < 600) {
                const int c  = e / 150;
                const int rr = e % 150;
                const int r  = rr / 50;
                const int cx = rr % 50;
                const int y   = h + r - 1;
                const int col = w0 + cx - 1;
                float v = 0.f;
                if ((unsigned)y < (unsigned)Hd && (unsigned)col < (unsigned)Wd)
                    v = __ldg(xb + (c0 + c) * HW_ + y * Wd + col);
                *reinterpret_cast<float2*>(&xr[buf][c][r][2 * cx]) = make_float2(v, v);
            }
        }
        __syncthreads();

#pragma unroll
        for (int c = 0; c < 4; c++) {
#pragma unroll
            for (int ki = 0; ki < 3; ki++) {
                unsigned long long rd[5];
#pragma unroll
                for (int q = 0; q < 5; q++)
                    rd[q] = *reinterpret_cast<const unsigned long long*>(
                                &xr[buf][c][ki][2 * (px0 + q)]);
#pragma unroll
                for (int kj = 0; kj < 3; kj++) {
                    ulonglong2 wp = *reinterpret_cast<const ulonglong2*>(
                                        &wA[buf][c][ki * 3 + kj][oc0]);
#pragma unroll
                    for (int j = 0; j < 3; j++) {
                        fma2(acc[0][j], wp.x, rd[kj + j]);
                        fma2(acc[1][j], wp.y, rd[kj + j]);
                    }
                }
            }
        }
    }

    // ---- epilogue (both packed lanes bounds-guarded)
#pragma unroll
    for (int i = 0; i < 2; i++)
#pragma unroll
        for (int j = 0; j < 3; j++) {
            float2 v = unpk(acc[i][j]);
            const int w = w0 + px0 + j;
            const int oce = oc0 + 2 * i;
            if (oce < 27)
                g_om[(b * 27 + oce) * HW_ + h * Wd + w] = v.x;
            if (oce + 1 < 27)
                g_om[(b * 27 + oce + 1) * HW_ + h * Wd + w] = v.y;
            if (oce < 18)
                outp[OUT_ELEMS + (b * 18 + oce) * HW_ + h * Wd + w] = v.x;
            if (oce + 1 < 18)
                outp[OUT_ELEMS + (b * 18 + oce + 1) * HW_ + h * Wd + w] = v.y;
        }
}

// ----------------------------------------------------------------------------
// Kernel 2: fused deformable im2col + GEMM, packed f32x2.
// Block tile: 128 oc x 64 px (flattened pixels), 128 thr.
// micro-tile: 8 oc (4 f32x2 pairs) x 8 px; ~125 regs -> no spill at (128,3).
// A-LDS dedups via broadcast; crossbar ~half of FMA pipe -> FMA-bound.
// Single sync per double-buffered KC=16 chunk; As via cp.async from g_wT.
// Grid: 4*144 = 576 blocks.
// ----------------------------------------------------------------------------
__global__ __launch_bounds__(128, 3) void dcn_main_kernel(
    const float* __restrict__ x,
    const float* __restrict__ bias,
    float* __restrict__ outp)
{
    __shared__ __align__(16) float  As[2][KC][132];   // [kk][oc]
    __shared__ __align__(16) float  Bs[2][KC][68];    // [kk][px]
    __shared__ __align__(8)  ushort4 sIdx[9 * 64];    // corner indices (u16)
    __shared__ __align__(16) float4  sWgt[9 * 64];    // corner weights
    __shared__ float sBias[128];

    const int bx = blockIdx.x;        // 0..575
    const int b  = bx / 144;
    const int P0 = (bx % 144) * 64;   // flattened pixel base within image
    const int t  = threadIdx.x;
    const int ty = t >> 3;            // 0..15 -> oc0 = ty*8
    const int tx = t & 7;             // 0..7  -> px0 = tx*8
    const int oc0 = ty * 8;
    const int px0 = tx * 8;

    sBias[t] = bias[t];

    // ---- precompute bilinear sampling metadata per (tap, pixel): 9 x 64
    for (int e = t; e < 9 * 64; e += 128) {
        const int k  = e >> 6;
        const int p  = e & 63;
        const int pp = P0 + p;                 // flattened pixel
        const int h  = pp / 96;
        const int w  = pp - h * 96;
        const float* om = g_om + (b * 27) * HW_ + pp;
        const float o1 = om[k * HW_];
        const float o2 = om[(9 + k) * HW_];
        const float mr = om[(18 + k) * HW_];
        const float m  = __fdividef(2.f, 1.f + __expf(-mr));

        const int ki = k / 3, kj = k - ki * 3;
        const float py  = (float)(h - 1 + ki) + o1;
        const float pxf = (float)(w - 1 + kj) + o2;
        const float y0f = floorf(py), x0f = floorf(pxf);
        const float ly = py - y0f, lx = pxf - x0f;
        const int y0 = (int)y0f, x0 = (int)x0f;
        const int y1 = y0 + 1,  x1 = x0 + 1;

        const float v00 = ((unsigned)y0 < (unsigned)Hd && (unsigned)x0 < (unsigned)Wd) ? 1.f : 0.f;
        const float v01 = ((unsigned)y0 < (unsigned)Hd && (unsigned)x1 < (unsigned)Wd) ? 1.f : 0.f;
        const float v10 = ((unsigned)y1 < (unsigned)Hd && (unsigned)x0 < (unsigned)Wd) ? 1.f : 0.f;
        const float v11 = ((unsigned)y1 < (unsigned)Hd && (unsigned)x1 < (unsigned)Wd) ? 1.f : 0.f;

        const int y0c = min(max(y0, 0), Hd - 1), y1c = min(max(y1, 0), Hd - 1);
        const int x0c = min(max(x0, 0), Wd - 1), x1c = min(max(x1, 0), Wd - 1);

        sIdx[e] = make_ushort4((unsigned short)(y0c * Wd + x0c),
                               (unsigned short)(y0c * Wd + x1c),
                               (unsigned short)(y1c * Wd + x0c),
                               (unsigned short)(y1c * Wd + x1c));
        const float hy = 1.f - ly, hx = 1.f - lx;
        sWgt[e] = make_float4(hy * hx * m * v00, hy * lx * m * v01,
                              ly * hx * m * v10, ly * lx * m * v11);
    }
    __syncthreads();

    unsigned long long acc[4][8];
#pragma unroll
    for (int i = 0; i < 4; i++)
#pragma unroll
        for (int j = 0; j < 8; j++) acc[i][j] = 0ull;

    const float* xb = x + b * CIN_ * HW_;
    int buf = 0;

    for (int kc = 0; kc < KKd; kc += KC, buf ^= 1) {
        // ---- As fill: 4x cp.async per thread (16 kk x 128 oc)
#pragma unroll
        for (int i = 0; i < 4; i++) {
            const int f   = t + i * 128;          // < 512
            const int kk  = f >> 5;
            const int oc4 = (f & 31) * 4;
            cp16(&As[buf][kk][oc4], g_wT + (kc + kk) * 128 + oc4);
        }
        cp_commit();
        // ---- Bs fill: deformable-sampled columns (16 kk x 64 px)
#pragma unroll
        for (int i = 0; i < 8; i++) {
            const int e    = t + i * 128;         // < 1024
            const int kk   = e >> 6;
            const int p    = e & 63;
            const int kidx = kc + kk;
            const int c    = kidx / 9;
            const int k    = kidx - c * 9;
            const ushort4 id = sIdx[(k << 6) + p];
            const float4  wv = sWgt[(k << 6) + p];
            const float* xc = xb + c * HW_;
            Bs[buf][kk][p] = wv.x * __ldg(xc + id.x)
                           + wv.y * __ldg(xc + id.y)
                           + wv.z * __ldg(xc + id.z)
                           + wv.w * __ldg(xc + id.w);
        }
        cp_wait0();
        __syncthreads();

        // ---- FMA over this chunk (fill of next chunk overlaps across warps)
#pragma unroll
        for (int kk = 0; kk < KC; kk++) {
            ulonglong2 aA = *reinterpret_cast<const ulonglong2*>(&As[buf][kk][oc0]);
            ulonglong2 aB = *reinterpret_cast<const ulonglong2*>(&As[buf][kk][oc0 + 4]);
            unsigned long long a[4] = {aA.x, aA.y, aB.x, aB.y};
            float4 b0 = *reinterpret_cast<const float4*>(&Bs[buf][kk][px0]);
            float4 b1 = *reinterpret_cast<const float4*>(&Bs[buf][kk][px0 + 4]);
            unsigned long long d[8] = {
                dup2(b0.x), dup2(b0.y), dup2(b0.z), dup2(b0.w),
                dup2(b1.x), dup2(b1.y), dup2(b1.z), dup2(b1.w)};
#pragma unroll
            for (int i = 0; i < 4; i++)
#pragma unroll
                for (int j = 0; j < 8; j++)
                    fma2(acc[i][j], a[i], d[j]);
        }
    }

    // ---- epilogue: unpack oc-pairs, add bias, store (pixel-flat contiguous)
#pragma unroll
    for (int i = 0; i < 4; i++) {
        const int oce = oc0 + 2 * i;
        const float be = sBias[oce];
        const float bo = sBias[oce + 1];
        float* pe = outp + (b * COUT_ + oce) * HW_ + P0 + px0;
        float* po = pe + HW_;
#pragma unroll
        for (int j = 0; j < 8; j++) {
            float2 v = unpk(acc[i][j]);
            pe[j] = v.x + be;
            po[j] = v.y + bo;
        }
    }
}

// ----------------------------------------------------------------------------
extern "C" void kernel_launch(void* const* d_in, const int* in_sizes, int n_in,
                              void* d_out, int out_size)
{
    const float* x    = (const float*)d_in[0];   // [4,128,96,96]
    const float* wgt  = (const float*)d_in[1];   // [128,128,3,3]
    const float* bias = (const float*)d_in[2];   // [128]
    const float* wom  = (const float*)d_in[3];   // [27,128,3,3]
    float* outp = (float*)d_out;

    offconv_kernel<<<768 + 288, 128>>>(x, wom, wgt, outp);  // conv + transpose
    dcn_main_kernel<<<Bn * 144, 128>>>(x, bias, outp);      // 576 blocks
}

// round 15
// speedup vs baseline: 1.3237x; 1.3237x over previous
#include <cuda_runtime.h>
#include <math.h>

// ----------------------------------------------------------------------------
// ModulatedDeformableConv2d (DCNv2-style) with residual offset output.
//   B=4, CIN=COUT=128, K=3, S=1, P=1, D=1, H=W=96, MASK_SCALE=2
// d_out: out [4,128,96,96] then offset [4,18,96,96], float32.
// ----------------------------------------------------------------------------

namespace {
constexpr int Bn    = 4;
constexpr int CIN_  = 128;
constexpr int COUT_ = 128;
constexpr int Hd    = 96;
constexpr int Wd    = 96;
constexpr int HW_   = 9216;
constexpr int KKd   = CIN_ * 9;              // 1152
constexpr int OUT_ELEMS = Bn * COUT_ * HW_;  // 4718592
constexpr int KC    = 16;                    // k-chunk
}

__device__ float g_om[Bn * 27 * HW_];             // offset/mask conv scratch
__device__ __align__(16) float g_wT [KKd * 128];  // weight transposed [kk][oc]
__device__ __align__(16) float g_wOmT[KKd * 32];  // w_offmask transposed [kk][oc<32]

// ---- packed fp32x2 + cp.async helpers --------------------------------------
__device__ __forceinline__ void fma2(unsigned long long& d,
                                     unsigned long long a,
                                     unsigned long long b) {
    asm("fma.rn.f32x2 %0, %1, %2, %0;" : "+l"(d) : "l"(a), "l"(b));
}
__device__ __forceinline__ unsigned long long dup2(float v) {
    unsigned long long r;
    asm("mov.b64 %0, {%1, %1};" : "=l"(r) : "f"(v));
    return r;
}
__device__ __forceinline__ float2 unpk(unsigned long long v) {
    float2 r;
    asm("mov.b64 {%0, %1}, %2;" : "=f"(r.x), "=f"(r.y) : "l"(v));
    return r;
}
__device__ __forceinline__ void cp16(void* dst_smem, const void* src) {
    unsigned d = (unsigned)__cvta_generic_to_shared(dst_smem);
    asm volatile("cp.async.ca.shared.global [%0], [%1], 16;" :: "r"(d), "l"(src));
}
__device__ __forceinline__ void cp_commit() {
    asm volatile("cp.async.commit_group;");
}
__device__ __forceinline__ void cp_wait0() {
    asm volatile("cp.async.wait_group 0;" ::: "memory");
}

// ----------------------------------------------------------------------------
// Kernel 0: one-time (per launch) weight transposes.
// ----------------------------------------------------------------------------
__global__ __launch_bounds__(256) void prep_kernel(
    const float* __restrict__ weight, const float* __restrict__ wom)
{
    const int idx = blockIdx.x * 256 + threadIdx.x;     // 0..184319
    if (idx < KKd * 128) {
        const int kk = idx >> 7, oc = idx & 127;
        g_wT[idx] = __ldg(weight + oc * KKd + kk);
    } else {
        const int j = idx - KKd * 128;
        const int kk = j >> 5, oc = j & 31;
        g_wOmT[j] = (oc < 27) ? __ldg(wom + oc * KKd + kk) : 0.f;
    }
}

// ----------------------------------------------------------------------------
// Kernel 1: om = conv3x3(x, w_offmask), 27 ch, pad=1.  (R8 version)
// ----------------------------------------------------------------------------
__global__ __launch_bounds__(128) void offconv_kernel(
    const float* __restrict__ x,
    float* __restrict__ outp)
{
    __shared__ __align__(16) float xr[2][4][3][104];  // dup-stored, cols 0..49
    __shared__ __align__(16) float wA[2][4][9][32];   // [c][tap][oc]

    const int bx = blockIdx.x;
    const int wt = bx & 1;
    const int h  = (bx >> 1) % Hd;
    const int b  = bx / (2 * Hd);
    const int w0 = wt * 48;
    const int t  = threadIdx.x;
    const int ty = t >> 4;            // 0..7  -> oc0 = ty*4
    const int tx = t & 15;            // 0..15 -> px0 = tx*3
    const int oc0 = ty * 4;
    const int px0 = tx * 3;

    unsigned long long acc[2][3];
#pragma unroll
    for (int i = 0; i < 2; i++)
#pragma unroll
        for (int j = 0; j < 3; j++) acc[i][j] = 0ull;

    const float* xb = x + b * CIN_ * HW_;
    int buf = 0;

    for (int c0 = 0; c0 < CIN_; c0 += 4, buf ^= 1) {
#pragma unroll
        for (int i = 0; i < 3; i++) {
            const int e = t + i * 128;
            if (e < 288) {
                const int c   = e / 72;
                const int rem = e % 72;
                const int tap = rem >> 3;
                const int oc4 = (rem & 7) * 4;
                cp16(&wA[buf][c][tap][oc4],
                     g_wOmT + ((c0 + c) * 9 + tap) * 32 + oc4);
            }
        }
        cp_commit();
#pragma unroll
        for (int i = 0; i < 5; i++) {
            const int e = t + i * 128;
            if (e < 600) {
                const int c  = e / 150;
                const int rr = e % 150;
                const int r  = rr / 50;
                const int cx = rr % 50;
                const int y   = h + r - 1;
                const int col = w0 + cx - 1;
                float v = 0.f;
                if ((unsigned)y < (unsigned)Hd && (unsigned)col < (unsigned)Wd)
                    v = __ldg(xb + (c0 + c) * HW_ + y * Wd + col);
                *reinterpret_cast<float2*>(&xr[buf][c][r][2 * cx]) = make_float2(v, v);
            }
        }
        cp_wait0();
        __syncthreads();

#pragma unroll
        for (int c = 0; c < 4; c++) {
#pragma unroll
            for (int ki = 0; ki < 3; ki++) {
                unsigned long long rd[5];
#pragma unroll
                for (int q = 0; q < 5; q++)
                    rd[q] = *reinterpret_cast<const unsigned long long*>(
                                &xr[buf][c][ki][2 * (px0 + q)]);
#pragma unroll
                for (int kj = 0; kj < 3; kj++) {
                    ulonglong2 wp = *reinterpret_cast<const ulonglong2*>(
                                        &wA[buf][c][ki * 3 + kj][oc0]);
#pragma unroll
                    for (int j = 0; j < 3; j++) {
                        fma2(acc[0][j], wp.x, rd[kj + j]);
                        fma2(acc[1][j], wp.y, rd[kj + j]);
                    }
                }
            }
        }
    }

    // ---- epilogue (both packed lanes bounds-guarded)
#pragma unroll
    for (int i = 0; i < 2; i++)
#pragma unroll
        for (int j = 0; j < 3; j++) {
            float2 v = unpk(acc[i][j]);
            const int w = w0 + px0 + j;
            const int oce = oc0 + 2 * i;
            if (oce < 27)
                g_om[(b * 27 + oce) * HW_ + h * Wd + w] = v.x;
            if (oce + 1 < 27)
                g_om[(b * 27 + oce + 1) * HW_ + h * Wd + w] = v.y;
            if (oce < 18)
                outp[OUT_ELEMS + (b * 18 + oce) * HW_ + h * Wd + w] = v.x;
            if (oce + 1 < 18)
                outp[OUT_ELEMS + (b * 18 + oce + 1) * HW_ + h * Wd + w] = v.y;
        }
}

// ----------------------------------------------------------------------------
// Kernel 2: fused deformable im2col + GEMM, packed f32x2.  (R8 geometry)
// Block tile: 128 oc x 48 px, 128 thr, micro 8 oc (4 pairs) x 6 px.
// Single sync per double-buffered KC=16 chunk; As via cp.async from g_wT.
// R13: 4 blocks/SM (regs capped at 128) for better latency hiding.
// ----------------------------------------------------------------------------
__global__ __launch_bounds__(128, 4) void dcn_main_kernel(
    const float* __restrict__ x,
    const float* __restrict__ bias,
    float* __restrict__ outp)
{
    __shared__ __align__(16) float  As[2][KC][132];   // [kk][oc]
    __shared__ __align__(16) float  Bs[2][KC][52];    // [kk][px]
    __shared__ __align__(8)  ushort4 sIdx[9 * 48];    // corner indices (u16)
    __shared__ __align__(16) float4  sWgt[9 * 48];    // corner weights
    __shared__ float sBias[128];

    const int bx = blockIdx.x;
    const int wt = bx & 1;
    const int h  = (bx >> 1) % Hd;
    const int b  = bx / (2 * Hd);
    const int w0 = wt * 48;
    const int t  = threadIdx.x;
    const int ty = t >> 3;            // 0..15 -> oc0 = ty*8
    const int tx = t & 7;             // 0..7  -> px0 = tx*6
    const int oc0 = ty * 8;
    const int px0 = tx * 6;

    sBias[t] = bias[t];

    // ---- precompute bilinear sampling metadata per (tap, pixel)
    for (int e = t; e < 9 * 48; e += 128) {
        const int k = e / 48;
        const int p = e % 48;
        const int w = w0 + p;
        const float* om = g_om + (b * 27) * HW_ + h * Wd + w;
        const float o1 = om[k * HW_];
        const float o2 = om[(9 + k) * HW_];
        const float mr = om[(18 + k) * HW_];
        const float m  = __fdividef(2.f, 1.f + __expf(-mr));

        const int ki = k / 3, kj = k - ki * 3;
        const float py  = (float)(h - 1 + ki) + o1;
        const float pxf = (float)(w - 1 + kj) + o2;
        const float y0f = floorf(py), x0f = floorf(pxf);
        const float ly = py - y0f, lx = pxf - x0f;
        const int y0 = (int)y0f, x0 = (int)x0f;
        const int y1 = y0 + 1,  x1 = x0 + 1;

        const float v00 = ((unsigned)y0 < (unsigned)Hd && (unsigned)x0 < (unsigned)Wd) ? 1.f : 0.f;
        const float v01 = ((unsigned)y0 < (unsigned)Hd && (unsigned)x1 < (unsigned)Wd) ? 1.f : 0.f;
        const float v10 = ((unsigned)y1 < (unsigned)Hd && (unsigned)x0 < (unsigned)Wd) ? 1.f : 0.f;
        const float v11 = ((unsigned)y1 < (unsigned)Hd && (unsigned)x1 < (unsigned)Wd) ? 1.f : 0.f;

        const int y0c = min(max(y0, 0), Hd - 1), y1c = min(max(y1, 0), Hd - 1);
        const int x0c = min(max(x0, 0), Wd - 1), x1c = min(max(x1, 0), Wd - 1);

        sIdx[e] = make_ushort4((unsigned short)(y0c * Wd + x0c),
                               (unsigned short)(y0c * Wd + x1c),
                               (unsigned short)(y1c * Wd + x0c),
                               (unsigned short)(y1c * Wd + x1c));
        const float hy = 1.f - ly, hx = 1.f - lx;
        sWgt[e] = make_float4(hy * hx * m * v00, hy * lx * m * v01,
                              ly * hx * m * v10, ly * lx * m * v11);
    }
    __syncthreads();

    unsigned long long acc[4][6];
#pragma unroll
    for (int i = 0; i < 4; i++)
#pragma unroll
        for (int j = 0; j < 6; j++) acc[i][j] = 0ull;

    const float* xb = x + b * CIN_ * HW_;
    int buf = 0;

    for (int kc = 0; kc < KKd; kc += KC, buf ^= 1) {
        // ---- As fill: 4x cp.async from pre-transposed weights
#pragma unroll
        for (int i = 0; i < 4; i++) {
            const int f   = t + i * 128;          // < 512
            const int kk  = f >> 5;
            const int oc4 = (f & 31) * 4;
            cp16(&As[buf][kk][oc4], g_wT + (kc + kk) * 128 + oc4);
        }
        cp_commit();
        // ---- Bs fill: deformable-sampled columns
#pragma unroll
        for (int i = 0; i < 6; i++) {
            const int e    = t + i * 128;         // < 768
            const int kk   = e / 48;
            const int p    = e % 48;
            const int kidx = kc + kk;
            const int c    = kidx / 9;
            const int k    = kidx - c * 9;
            const ushort4 id = sIdx[k * 48 + p];
            const float4  wv = sWgt[k * 48 + p];
            const float* xc = xb + c * HW_;
            Bs[buf][kk][p] = wv.x * __ldg(xc + id.x)
                           + wv.y * __ldg(xc + id.y)
                           + wv.z * __ldg(xc + id.z)
                           + wv.w * __ldg(xc + id.w);
        }
        cp_wait0();
        __syncthreads();

        // ---- FMA over this chunk (fill of next chunk overlaps across warps)
#pragma unroll
        for (int kk = 0; kk < KC; kk++) {
            ulonglong2 aA = *reinterpret_cast<const ulonglong2*>(&As[buf][kk][oc0]);
            ulonglong2 aB = *reinterpret_cast<const ulonglong2*>(&As[buf][kk][oc0 + 4]);
            float2 b0 = *reinterpret_cast<const float2*>(&Bs[buf][kk][px0]);
            float2 b1 = *reinterpret_cast<const float2*>(&Bs[buf][kk][px0 + 2]);
            float2 b2 = *reinterpret_cast<const float2*>(&Bs[buf][kk][px0 + 4]);
            unsigned long long a[4] = {aA.x, aA.y, aB.x, aB.y};
            unsigned long long d[6] = {dup2(b0.x), dup2(b0.y), dup2(b1.x),
                                       dup2(b1.y), dup2(b2.x), dup2(b2.y)};
#pragma unroll
            for (int i = 0; i < 4; i++)
#pragma unroll
                for (int j = 0; j < 6; j++)
                    fma2(acc[i][j], a[i], d[j]);
        }
    }

    // ---- epilogue: unpack oc-pairs, add bias, store
    const int w = w0 + px0;
#pragma unroll
    for (int i = 0; i < 4; i++) {
        const int oce = oc0 + 2 * i;
        const float be = sBias[oce];
        const float bo = sBias[oce + 1];
        float* pe = outp + (b * COUT_ + oce) * HW_ + h * Wd + w;
        float* po = pe + HW_;
#pragma unroll
        for (int j = 0; j < 6; j++) {
            float2 v = unpk(acc[i][j]);
            pe[j] = v.x + be;
            po[j] = v.y + bo;
        }
    }
}

// ----------------------------------------------------------------------------
extern "C" void kernel_launch(void* const* d_in, const int* in_sizes, int n_in,
                              void* d_out, int out_size)
{
    const float* x    = (const float*)d_in[0];   // [4,128,96,96]
    const float* wgt  = (const float*)d_in[1];   // [128,128,3,3]
    const float* bias = (const float*)d_in[2];   // [128]
    const float* wom  = (const float*)d_in[3];   // [27,128,3,3]
    float* outp = (float*)d_out;

    prep_kernel<<<720, 256>>>(wgt, wom);                   // transposes
    offconv_kernel<<<Bn * Hd * 2, 128>>>(x, outp);         // 768 blocks
    dcn_main_kernel<<<Bn * Hd * 2, 128>>>(x, bias, outp);  // 768 blocks
}